// round 7
// baseline (speedup 1.0000x reference)
#include <cuda_runtime.h>
#include <cstdint>

#define Bsz 128
#define Lseq 1024
#define Hd 256
#define G3 768
#define CLS 8
#define RSTF 260          // float stride per w/h row (256 + 4 pad -> 4-bank stagger)
#define HBUF (8 * RSTF)   // one h buffer: 8 batches

typedef unsigned long long u64;

__device__ __forceinline__ u64 f2fma(u64 a, u64 b, u64 c) {
    u64 d; asm("fma.rn.f32x2 %0, %1, %2, %3;" : "=l"(d) : "l"(a), "l"(b), "l"(c)); return d;
}
__device__ __forceinline__ u64 f2add(u64 a, u64 b) {
    u64 d; asm("add.rn.f32x2 %0, %1, %2;" : "=l"(d) : "l"(a), "l"(b)); return d;
}
__device__ __forceinline__ u64 dup2(float x) {
    u64 r; asm("mov.b64 %0, {%1, %1};" : "=l"(r) : "f"(x)); return r;
}
__device__ __forceinline__ void up2(u64 v, float& lo, float& hi) {
    asm("mov.b64 {%0, %1}, %2;" : "=f"(lo), "=f"(hi) : "l"(v));
}
__device__ __forceinline__ float hsum2(u64 v) {
    float lo, hi; up2(v, lo, hi); return lo + hi;
}
__device__ __forceinline__ uint32_t smem_u32(const void* p) {
    uint32_t a;
    asm("{ .reg .u64 t; cvta.to.shared.u64 t, %1; cvt.u32.u64 %0, t; }" : "=r"(a) : "l"(p));
    return a;
}
__device__ __forceinline__ uint32_t cta_rank() {
    uint32_t r; asm("mov.u32 %0, %%cluster_ctarank;" : "=r"(r)); return r;
}

// ---------------- scratch ----------------
__device__ float g_gi[(size_t)Lseq * G3 * Bsz];      // [t][3H][B]
__device__ float g_hseq0[(size_t)Lseq * Hd * Bsz];   // [t][k][b]
__device__ float g_hseq1[(size_t)Lseq * Hd * Bsz];

// ---------------- input-side GEMM: Gi[t][c][b] ----------------
__global__ __launch_bounds__(256) void gi_gemm_kernel(
    const float* __restrict__ xin, const float* __restrict__ W,
    const float* __restrict__ bias, int layer)
{
    __shared__ float Ws[16 * 132];
    __shared__ float As[16 * 132];

    const int t  = blockIdx.y;
    const int c0 = blockIdx.x * 128;
    const int tid = threadIdx.x;
    const int ty = tid >> 4;
    const int tx = tid & 15;

    u64 acc2[8][4];
#pragma unroll
    for (int i = 0; i < 8; i++)
#pragma unroll
        for (int j = 0; j < 4; j++) acc2[i][j] = 0ull;

    for (int k0 = 0; k0 < 256; k0 += 16) {
        {
            int row  = tid >> 2;
            int col4 = (tid & 3) * 4;
#pragma unroll
            for (int it = 0; it < 2; it++, row += 64) {
                float4 w = *(const float4*)(W + (size_t)(c0 + row) * 256 + k0 + col4);
                Ws[(col4 + 0) * 132 + row] = w.x;
                Ws[(col4 + 1) * 132 + row] = w.y;
                Ws[(col4 + 2) * 132 + row] = w.z;
                Ws[(col4 + 3) * 132 + row] = w.w;
            }
        }
        if (layer == 0) {
            int row  = tid >> 2;
            int col4 = (tid & 3) * 4;
#pragma unroll
            for (int it = 0; it < 2; it++, row += 64) {
                float4 a = *(const float4*)(xin + ((size_t)row * Lseq + t) * 256 + k0 + col4);
                As[(col4 + 0) * 132 + row] = a.x;
                As[(col4 + 1) * 132 + row] = a.y;
                As[(col4 + 2) * 132 + row] = a.z;
                As[(col4 + 3) * 132 + row] = a.w;
            }
        } else {
#pragma unroll
            for (int it = 0; it < 2; it++) {
                int idx = tid + it * 256;
                int k  = idx >> 5;
                int b4 = (idx & 31) * 4;
                float4 a = *(const float4*)(g_hseq0 + ((size_t)t * 256 + k0 + k) * 128 + b4);
                *(float4*)(As + k * 132 + b4) = a;
            }
        }
        __syncthreads();

#pragma unroll
        for (int kk = 0; kk < 16; kk++) {
            float wr[8];
            *(float4*)(wr)     = *(const float4*)(Ws + kk * 132 + ty * 4);
            *(float4*)(wr + 4) = *(const float4*)(Ws + kk * 132 + 64 + ty * 4);
            ulonglong2 aA = *(const ulonglong2*)(As + kk * 132 + tx * 4);
            ulonglong2 aB = *(const ulonglong2*)(As + kk * 132 + 64 + tx * 4);
#pragma unroll
            for (int i = 0; i < 8; i++) {
                u64 wd = dup2(wr[i]);
                acc2[i][0] = f2fma(aA.x, wd, acc2[i][0]);
                acc2[i][1] = f2fma(aA.y, wd, acc2[i][1]);
                acc2[i][2] = f2fma(aB.x, wd, acc2[i][2]);
                acc2[i][3] = f2fma(aB.y, wd, acc2[i][3]);
            }
        }
        __syncthreads();
    }

    float* gout = g_gi + (size_t)t * G3 * Bsz;
#pragma unroll
    for (int i = 0; i < 8; i++) {
        int c = (i < 4) ? (c0 + ty * 4 + i) : (c0 + 64 + ty * 4 + (i - 4));
        float bv = bias[c];
        float a0, a1, a2, a3, a4, a5, a6, a7;
        up2(acc2[i][0], a0, a1); up2(acc2[i][1], a2, a3);
        up2(acc2[i][2], a4, a5); up2(acc2[i][3], a6, a7);
        *(float4*)(gout + (size_t)c * Bsz + tx * 4) =
            make_float4(a0 + bv, a1 + bv, a2 + bv, a3 + bv);
        *(float4*)(gout + (size_t)c * Bsz + 64 + tx * 4) =
            make_float4(a4 + bv, a5 + bv, a6 + bv, a7 + bv);
    }
}

// ---------------- persistent GRU recurrence, cluster + broadcast-LDS ----------------
// grid 128, cluster 8. Cluster cl: batches [cl*8, cl*8+8). CTA rank: hidden
// units [rank*32, rank*32+32), all 3 gates. 256 threads = 32 j x 8 b; each
// thread computes one (j, b) over full K. Warp = 8 b x 4 j -> every LDS is a
// single crossbar phase. No __syncthreads in the step loop; one
// barrier.cluster per step orders the DSMEM h broadcast.
__global__ __launch_bounds__(256, 1) __cluster_dims__(CLS, 1, 1)
void gru_recur_kernel(
    const float* __restrict__ w_hh, const float* __restrict__ b_hh,
    const float* __restrict__ h0all, int layer)
{
    extern __shared__ __align__(16) float sm[];
    float* w_s  = sm;                     // 96 rows * RSTF
    float* h_s  = sm + 96 * RSTF;         // 2 * HBUF
    float* bh_s = h_s + 2 * HBUF;         // 96

    const int tid  = threadIdx.x;
    const uint32_t rank = cta_rank();
    const int cl = blockIdx.x >> 3;
    const int b0 = cl * 8;
    const int j0 = (int)rank * 32;

    float* hseq = layer ? g_hseq1 : g_hseq0;

    // stage weights: w_s[g*32+j][k], coalesced over k
    for (int i = tid; i < 96 * 256; i += 256) {
        int row = i >> 8;                 // 0..95
        int k   = i & 255;
        int g = row >> 5, j = row & 31;
        w_s[row * RSTF + k] = w_hh[(size_t)(g * 256 + j0 + j) * 256 + k];
    }
    if (tid < 96)
        bh_s[tid] = b_hh[(tid >> 5) * 256 + j0 + (tid & 31)];
    // stage h0 into buffer 0
    {
        const float* h0g = h0all + (size_t)layer * Bsz * Hd;  // [b][k]
        for (int i = tid; i < 8 * 256; i += 256) {
            int bb = i >> 8, k = i & 255;
            h_s[bb * RSTF + k] = h0g[(size_t)(b0 + bb) * 256 + k];
        }
    }
    __syncthreads();
    asm volatile("barrier.cluster.arrive.aligned;" ::: "memory");
    asm volatile("barrier.cluster.wait.aligned;" ::: "memory");

    const int b    = tid & 7;
    const int jsub = (tid >> 3) & 3;
    const int warp = tid >> 5;
    const int j    = warp * 4 + jsub;

    const float* wr = w_s + (0 * 32 + j) * RSTF;
    const float* wz = w_s + (32 + j) * RSTF;
    const float* wn = w_s + (64 + j) * RSTF;
    const float bhr = bh_s[j], bhz = bh_s[32 + j], bhn = bh_s[64 + j];

    // precomputed remote DSMEM addresses for both buffers
    uint32_t ra0[CLS], ra1[CLS];
    {
        uint32_t la0 = smem_u32(h_s + b * RSTF + j0 + j);
        uint32_t la1 = la0 + HBUF * 4;
#pragma unroll
        for (int r = 0; r < CLS; r++) {
            asm("mapa.shared::cluster.u32 %0, %1, %2;" : "=r"(ra0[r]) : "r"(la0), "r"(r));
            asm("mapa.shared::cluster.u32 %0, %1, %2;" : "=r"(ra1[r]) : "r"(la1), "r"(r));
        }
    }

    const size_t gx = (size_t)(j0 + j) * Bsz + b0 + b;
    float gir = g_gi[gx], giz = g_gi[32768 + gx], gin = g_gi[65536 + gx];

    for (int t = 0; t < Lseq; t++) {
        const int p = t & 1;
        const float* hb = h_s + p * HBUF + b * RSTF;

        u64 ar0 = 0, ar1 = 0, az0 = 0, az1 = 0, an0 = 0, an1 = 0;
#pragma unroll
        for (int c = 0; c < 256; c += 8) {
            ulonglong2 h01 = *(const ulonglong2*)(hb + c);
            ulonglong2 h23 = *(const ulonglong2*)(hb + c + 4);
            ulonglong2 r01 = *(const ulonglong2*)(wr + c);
            ulonglong2 r23 = *(const ulonglong2*)(wr + c + 4);
            ulonglong2 z01 = *(const ulonglong2*)(wz + c);
            ulonglong2 z23 = *(const ulonglong2*)(wz + c + 4);
            ulonglong2 n01 = *(const ulonglong2*)(wn + c);
            ulonglong2 n23 = *(const ulonglong2*)(wn + c + 4);
            ar0 = f2fma(h01.x, r01.x, ar0); ar1 = f2fma(h01.y, r01.y, ar1);
            ar0 = f2fma(h23.x, r23.x, ar0); ar1 = f2fma(h23.y, r23.y, ar1);
            az0 = f2fma(h01.x, z01.x, az0); az1 = f2fma(h01.y, z01.y, az1);
            az0 = f2fma(h23.x, z23.x, az0); az1 = f2fma(h23.y, z23.y, az1);
            an0 = f2fma(h01.x, n01.x, an0); an1 = f2fma(h01.y, n01.y, an1);
            an0 = f2fma(h23.x, n23.x, an0); an1 = f2fma(h23.y, n23.y, an1);
        }
        float gr = hsum2(f2add(ar0, ar1)) + bhr;
        float gz = hsum2(f2add(az0, az1)) + bhz;
        float gn = hsum2(f2add(an0, an1)) + bhn;

        float er = __expf(-(gir + gr));
        float ez = __expf(-(giz + gz));
        float r = __fdividef(1.0f, 1.0f + er);
        float z = __fdividef(1.0f, 1.0f + ez);
        float xn = gin + r * gn;
        float e2 = __expf(2.0f * xn);
        float n = 1.0f - __fdividef(2.0f, e2 + 1.0f);

        float hprev = hb[j0 + j];
        float hnew = (1.0f - z) * n + z * hprev;

        hseq[(size_t)t * (Hd * Bsz) + gx] = hnew;

        // DSMEM broadcast into buffer p^1 of every CTA in the cluster
        const uint32_t* ra = (p ? ra0 : ra1);
#pragma unroll
        for (int rr = 0; rr < CLS; rr++) {
            asm volatile("st.shared::cluster.f32 [%0], %1;"
                         :: "r"(ra[rr]), "f"(hnew) : "memory");
        }

        asm volatile("barrier.cluster.arrive.aligned;" ::: "memory");
        if (t + 1 < Lseq) {
            const float* gi_n1 = g_gi + (size_t)(t + 1) * (G3 * Bsz);
            gir = gi_n1[gx];
            giz = gi_n1[32768 + gx];
            gin = gi_n1[65536 + gx];
        }
        asm volatile("barrier.cluster.wait.aligned;" ::: "memory");
    }
}

// ---------------- transpose g_hseq1 [t][h][b] -> out [b][t][h] ----------------
__global__ __launch_bounds__(256) void transpose_out_kernel(float* __restrict__ out)
{
    __shared__ float tile[32 * 129];
    const int t  = blockIdx.y;
    const int h0 = blockIdx.x * 32;
    const int tid = threadIdx.x;
    const float* src = g_hseq1 + (size_t)t * (Hd * Bsz) + (size_t)h0 * Bsz;

    for (int idx = tid; idx < 4096; idx += 256) {
        int hh = idx >> 7, bb = idx & 127;
        tile[hh * 129 + bb] = src[idx];
    }
    __syncthreads();
    for (int idx = tid; idx < 4096; idx += 256) {
        int bb = idx >> 5, hh = idx & 31;
        out[(size_t)bb * Lseq * Hd + (size_t)t * Hd + h0 + hh] = tile[hh * 129 + bb];
    }
}

// ---------------- final hidden states ----------------
__global__ __launch_bounds__(256) void hn_kernel(float* __restrict__ out)
{
    int idx = blockIdx.x * blockDim.x + threadIdx.x;  // 0..65535
    int layer = idx >> 15;
    int b = (idx >> 8) & 127;
    int h = idx & 255;
    const float* hs = layer ? g_hseq1 : g_hseq0;
    out[(size_t)Bsz * Lseq * Hd + idx] =
        hs[(size_t)(Lseq - 1) * (Hd * Bsz) + (size_t)h * Bsz + b];
}

// ---------------- launcher ----------------
extern "C" void kernel_launch(void* const* d_in, const int* in_sizes, int n_in,
                              void* d_out, int out_size)
{
    const float* x     = (const float*)d_in[0];
    const float* h0    = (const float*)d_in[1];
    const float* w_ih0 = (const float*)d_in[2];
    const float* w_hh0 = (const float*)d_in[3];
    const float* b_ih0 = (const float*)d_in[4];
    const float* b_hh0 = (const float*)d_in[5];
    const float* w_ih1 = (const float*)d_in[6];
    const float* w_hh1 = (const float*)d_in[7];
    const float* b_ih1 = (const float*)d_in[8];
    const float* b_hh1 = (const float*)d_in[9];
    float* out = (float*)d_out;

    const size_t smem = (96 * RSTF + 2 * HBUF + 128) * sizeof(float);  // ~116.9 KB
    cudaFuncSetAttribute(gru_recur_kernel,
                         cudaFuncAttributeMaxDynamicSharedMemorySize, (int)smem);

    gi_gemm_kernel<<<dim3(6, Lseq), 256>>>(x, w_ih0, b_ih0, 0);
    gru_recur_kernel<<<128, 256, smem>>>(w_hh0, b_hh0, h0, 0);
    gi_gemm_kernel<<<dim3(6, Lseq), 256>>>(x, w_ih1, b_ih1, 1);
    gru_recur_kernel<<<128, 256, smem>>>(w_hh1, b_hh1, h0, 1);
    transpose_out_kernel<<<dim3(8, Lseq), 256>>>(out);
    if (out_size >= (int)((size_t)Bsz * Lseq * Hd + 2 * Bsz * Hd))
        hn_kernel<<<256, 256>>>(out);
}

// round 8
// speedup vs baseline: 2.2523x; 2.2523x over previous
#include <cuda_runtime.h>
#include <cstdint>

#define Bsz 128
#define Lseq 1024
#define Hd 256
#define G3 768
#define RBLK 128
#define W2S 258   // u64 stride per duplicated-weight row

typedef unsigned long long u64;

__device__ __forceinline__ u64 f2fma(u64 a, u64 b, u64 c) {
    u64 d; asm("fma.rn.f32x2 %0, %1, %2, %3;" : "=l"(d) : "l"(a), "l"(b), "l"(c)); return d;
}
__device__ __forceinline__ u64 f2add(u64 a, u64 b) {
    u64 d; asm("add.rn.f32x2 %0, %1, %2;" : "=l"(d) : "l"(a), "l"(b)); return d;
}
__device__ __forceinline__ u64 dup2(float x) {
    u64 r; asm("mov.b64 %0, {%1, %1};" : "=l"(r) : "f"(x)); return r;
}
__device__ __forceinline__ void up2(u64 v, float& lo, float& hi) {
    asm("mov.b64 {%0, %1}, %2;" : "=f"(lo), "=f"(hi) : "l"(v));
}

// ---------------- scratch ----------------
__device__ float g_gi[(size_t)Lseq * G3 * Bsz];      // [t][3H][B]
__device__ float g_hseq0[(size_t)Lseq * Hd * Bsz];   // [t][k][b]
__device__ float g_hseq1[(size_t)Lseq * Hd * Bsz];

// 4 independent group barriers (one per bt), 128B-strided counters
__device__ unsigned g_cnt4[4 * 32];
__device__ unsigned g_gen4[4 * 32];

// ---------------- input-side GEMM: Gi[t][c][b] ----------------
__global__ __launch_bounds__(256) void gi_gemm_kernel(
    const float* __restrict__ xin, const float* __restrict__ W,
    const float* __restrict__ bias, int layer)
{
    __shared__ float Ws[16 * 132];
    __shared__ float As[16 * 132];

    const int t  = blockIdx.y;
    const int c0 = blockIdx.x * 128;
    const int tid = threadIdx.x;
    const int ty = tid >> 4;
    const int tx = tid & 15;

    u64 acc2[8][4];
#pragma unroll
    for (int i = 0; i < 8; i++)
#pragma unroll
        for (int j = 0; j < 4; j++) acc2[i][j] = 0ull;

    for (int k0 = 0; k0 < 256; k0 += 16) {
        {
            int row  = tid >> 2;
            int col4 = (tid & 3) * 4;
#pragma unroll
            for (int it = 0; it < 2; it++, row += 64) {
                float4 w = *(const float4*)(W + (size_t)(c0 + row) * 256 + k0 + col4);
                Ws[(col4 + 0) * 132 + row] = w.x;
                Ws[(col4 + 1) * 132 + row] = w.y;
                Ws[(col4 + 2) * 132 + row] = w.z;
                Ws[(col4 + 3) * 132 + row] = w.w;
            }
        }
        if (layer == 0) {
            int row  = tid >> 2;
            int col4 = (tid & 3) * 4;
#pragma unroll
            for (int it = 0; it < 2; it++, row += 64) {
                float4 a = *(const float4*)(xin + ((size_t)row * Lseq + t) * 256 + k0 + col4);
                As[(col4 + 0) * 132 + row] = a.x;
                As[(col4 + 1) * 132 + row] = a.y;
                As[(col4 + 2) * 132 + row] = a.z;
                As[(col4 + 3) * 132 + row] = a.w;
            }
        } else {
#pragma unroll
            for (int it = 0; it < 2; it++) {
                int idx = tid + it * 256;
                int k  = idx >> 5;
                int b4 = (idx & 31) * 4;
                float4 a = *(const float4*)(g_hseq0 + ((size_t)t * 256 + k0 + k) * 128 + b4);
                *(float4*)(As + k * 132 + b4) = a;
            }
        }
        __syncthreads();

#pragma unroll
        for (int kk = 0; kk < 16; kk++) {
            float wr[8];
            *(float4*)(wr)     = *(const float4*)(Ws + kk * 132 + ty * 4);
            *(float4*)(wr + 4) = *(const float4*)(Ws + kk * 132 + 64 + ty * 4);
            ulonglong2 aA = *(const ulonglong2*)(As + kk * 132 + tx * 4);
            ulonglong2 aB = *(const ulonglong2*)(As + kk * 132 + 64 + tx * 4);
#pragma unroll
            for (int i = 0; i < 8; i++) {
                u64 wd = dup2(wr[i]);
                acc2[i][0] = f2fma(aA.x, wd, acc2[i][0]);
                acc2[i][1] = f2fma(aA.y, wd, acc2[i][1]);
                acc2[i][2] = f2fma(aB.x, wd, acc2[i][2]);
                acc2[i][3] = f2fma(aB.y, wd, acc2[i][3]);
            }
        }
        __syncthreads();
    }

    float* gout = g_gi + (size_t)t * G3 * Bsz;
#pragma unroll
    for (int i = 0; i < 8; i++) {
        int c = (i < 4) ? (c0 + ty * 4 + i) : (c0 + 64 + ty * 4 + (i - 4));
        float bv = bias[c];
        float a0, a1, a2, a3, a4, a5, a6, a7;
        up2(acc2[i][0], a0, a1); up2(acc2[i][1], a2, a3);
        up2(acc2[i][2], a4, a5); up2(acc2[i][3], a6, a7);
        *(float4*)(gout + (size_t)c * Bsz + tx * 4) =
            make_float4(a0 + bv, a1 + bv, a2 + bv, a3 + bv);
        *(float4*)(gout + (size_t)c * Bsz + 64 + tx * 4) =
            make_float4(a4 + bv, a5 + bv, a6 + bv, a7 + bv);
    }
}

// ---------------- persistent GRU recurrence (R4 shape + group barriers) ----------------
// 128 blocks x 512 threads. Block tile: 32 b x 8 j (24 gate rows).
// Thread: bq = tid&7 (4 batches via 2x f32x2), j = (tid>>3)&7, kq = tid>>6 (32 k).
__global__ __launch_bounds__(512) void gru_recur_kernel(
    const float* __restrict__ w_hh, const float* __restrict__ b_hh,
    const float* __restrict__ h0all, int layer)
{
    extern __shared__ __align__(16) char smraw[];
    u64*   w2_s  = (u64*)smraw;            // 24*258 = 6192 u64
    u64*   red_s = w2_s + 6192;            // 8 kq * 384 = 3072 u64
    float* h_s   = (float*)(red_s + 3072); // 256 k * 32 b = 8192 floats
    float* red2  = h_s + 8192;             // 768 floats
    float* bh_s  = red2 + 768;             // 24 (+pad)

    const int tid = threadIdx.x;
    const int bt = blockIdx.x >> 5;
    const int ht = blockIdx.x & 31;
    const int b0 = bt * 32;
    const int j0 = ht * 8;

    float* hseq = layer ? g_hseq1 : g_hseq0;
    unsigned* cnt_p = &g_cnt4[bt * 32];
    unsigned* gen_p = &g_gen4[bt * 32];

    // duplicated persistent weights
    for (int idx = tid; idx < 6144; idx += 512) {
        int gj = idx >> 8;
        int k  = idx & 255;
        int g  = gj >> 3, j = gj & 7;
        w2_s[gj * W2S + k] = dup2(__ldg(w_hh + (size_t)(g * 256 + j0 + j) * 256 + k));
    }
    if (tid < 24) {
        int g = tid >> 3, j = tid & 7;
        bh_s[tid] = b_hh[g * 256 + j0 + j];
    }

    unsigned gen;
    asm volatile("ld.acquire.gpu.u32 %0, [%1];" : "=r"(gen) : "l"(gen_p) : "memory");
    __syncthreads();

    const int bq = tid & 7;
    const int j  = (tid >> 3) & 7;
    const int kq = tid >> 6;
    const int kbase = kq * 32;

    const u64* wrp = w2_s + (0 + j) * W2S + kbase;
    const u64* wzp = w2_s + (8 + j) * W2S + kbase;
    const u64* wnp = w2_s + (16 + j) * W2S + kbase;
    const float* hb = h_s + kbase * 32 + bq * 4;

    // activation-thread mapping (tid < 256)
    const int ab = tid & 31;
    const int aj = (tid >> 5) & 7;
    const size_t gidx = (size_t)(j0 + aj) * Bsz + b0 + ab;

    float cir = 0.f, ciz = 0.f, cin_ = 0.f;
    if (tid < 256) {
        cir  = __ldg(g_gi + gidx);
        ciz  = __ldg(g_gi + 32768 + gidx);
        cin_ = __ldg(g_gi + 65536 + gidx);
    }

    for (int t = 0; t < Lseq; t++) {
        // ---- stage h_prev into h_s[k][b32] ----
        if (t == 0) {
            const float* h0g = h0all + (size_t)layer * Bsz * Hd;  // [b][k]
            for (int i = tid; i < 8192; i += 512) {
                int k = i >> 5, bb = i & 31;
                h_s[k * 32 + bb] = h0g[(size_t)(b0 + bb) * 256 + k];
            }
        } else {
            const float* src = hseq + (size_t)(t - 1) * (Hd * Bsz);
#pragma unroll
            for (int u = 0; u < 4; u++) {
                int i = tid + u * 512;
                int k = i >> 3, c = i & 7;
                float4 v = __ldg((const float4*)(src + (size_t)k * Bsz + b0 + c * 4));
                *(float4*)(h_s + k * 32 + c * 4) = v;
            }
        }
        __syncthreads();

        // ---- partial dot over this thread's 32 k (f32x2 over batch) ----
        u64 ar0 = 0, ar1 = 0, az0 = 0, az1 = 0, an0 = 0, an1 = 0;
#pragma unroll
        for (int i = 0; i < 32; i += 2) {
            ulonglong2 ha = *(const ulonglong2*)(hb + i * 32);
            ulonglong2 hc = *(const ulonglong2*)(hb + i * 32 + 32);
            ulonglong2 wr = *(const ulonglong2*)(wrp + i);
            ulonglong2 wz = *(const ulonglong2*)(wzp + i);
            ulonglong2 wn = *(const ulonglong2*)(wnp + i);
            ar0 = f2fma(ha.x, wr.x, ar0); ar1 = f2fma(ha.y, wr.x, ar1);
            ar0 = f2fma(hc.x, wr.y, ar0); ar1 = f2fma(hc.y, wr.y, ar1);
            az0 = f2fma(ha.x, wz.x, az0); az1 = f2fma(ha.y, wz.x, az1);
            az0 = f2fma(hc.x, wz.y, az0); az1 = f2fma(hc.y, wz.y, az1);
            an0 = f2fma(ha.x, wn.x, an0); an1 = f2fma(ha.y, wn.x, an1);
            an0 = f2fma(hc.x, wn.y, an0); an1 = f2fma(hc.y, wn.y, an1);
        }
        {
            u64* rb = red_s + (size_t)kq * 384 + (j * 8 + bq) * 2;
            *(ulonglong2*)(rb)       = make_ulonglong2(ar0, ar1);
            *(ulonglong2*)(rb + 128) = make_ulonglong2(az0, az1);
            *(ulonglong2*)(rb + 256) = make_ulonglong2(an0, an1);
        }
        __syncthreads();

        // ---- reduce over kq: 192 threads ----
        if (tid < 192) {
            u64 s0 = 0, s1 = 0;
            const u64* base = red_s + tid * 2;
#pragma unroll
            for (int q = 0; q < 8; q++) {
                ulonglong2 v = *(const ulonglong2*)(base + q * 384);
                s0 = f2add(s0, v.x);
                s1 = f2add(s1, v.y);
            }
            int g = tid >> 6, jj = (tid >> 3) & 7, bb = tid & 7;
            float l0, h0f, l1, h1f;
            up2(s0, l0, h0f); up2(s1, l1, h1f);
            *(float4*)(red2 + (g * 8 + jj) * 32 + bb * 4) = make_float4(l0, h0f, l1, h1f);
        }
        __syncthreads();

        // ---- activation + write hnew: 256 threads ----
        if (tid < 256) {
            float gr = red2[aj * 32 + ab]        + bh_s[aj];
            float gz = red2[(8 + aj) * 32 + ab]  + bh_s[8 + aj];
            float gn = red2[(16 + aj) * 32 + ab] + bh_s[16 + aj];
            float r = 1.0f / (1.0f + __expf(-(cir + gr)));
            float z = 1.0f / (1.0f + __expf(-(ciz + gz)));
            float n = tanhf(cin_ + r * gn);
            float hprev = h_s[(j0 + aj) * 32 + ab];
            float hnew = (1.0f - z) * n + z * hprev;
            hseq[(size_t)t * (Hd * Bsz) + (size_t)(j0 + aj) * Bsz + b0 + ab] = hnew;
        }
        __syncthreads();

        // ---- group barrier (32 blocks, acquire/release) ----
        unsigned target = gen + 1;
        if (tid == 0) {
            unsigned old;
            asm volatile("atom.release.gpu.add.u32 %0, [%1], %2;"
                         : "=r"(old) : "l"(cnt_p), "r"(1u) : "memory");
            if (old == 31u) {
                asm volatile("st.relaxed.gpu.u32 [%0], %1;" :: "l"(cnt_p), "r"(0u) : "memory");
                asm volatile("st.release.gpu.u32 [%0], %1;" :: "l"(gen_p), "r"(target) : "memory");
            }
        }
        // prefetch next-step gi during barrier skew
        if (tid < 256 && t + 1 < Lseq) {
            const float* gi_n = g_gi + (size_t)(t + 1) * (G3 * Bsz);
            cir  = __ldg(gi_n + gidx);
            ciz  = __ldg(gi_n + 32768 + gidx);
            cin_ = __ldg(gi_n + 65536 + gidx);
        }
        if (tid == 0) {
            unsigned v;
            do {
                asm volatile("ld.acquire.gpu.u32 %0, [%1];" : "=r"(v) : "l"(gen_p) : "memory");
            } while (v != target);
        }
        gen = target;
        __syncthreads();
    }
}

// ---------------- transpose g_hseq1 [t][h][b] -> out [b][t][h] ----------------
__global__ __launch_bounds__(256) void transpose_out_kernel(float* __restrict__ out)
{
    __shared__ float tile[32 * 129];
    const int t  = blockIdx.y;
    const int h0 = blockIdx.x * 32;
    const int tid = threadIdx.x;
    const float* src = g_hseq1 + (size_t)t * (Hd * Bsz) + (size_t)h0 * Bsz;

    for (int idx = tid; idx < 4096; idx += 256) {
        int hh = idx >> 7, bb = idx & 127;
        tile[hh * 129 + bb] = src[idx];
    }
    __syncthreads();
    for (int idx = tid; idx < 4096; idx += 256) {
        int bb = idx >> 5, hh = idx & 31;
        out[(size_t)bb * Lseq * Hd + (size_t)t * Hd + h0 + hh] = tile[hh * 129 + bb];
    }
}

// ---------------- final hidden states ----------------
__global__ __launch_bounds__(256) void hn_kernel(float* __restrict__ out)
{
    int idx = blockIdx.x * blockDim.x + threadIdx.x;  // 0..65535
    int layer = idx >> 15;
    int b = (idx >> 8) & 127;
    int h = idx & 255;
    const float* hs = layer ? g_hseq1 : g_hseq0;
    out[(size_t)Bsz * Lseq * Hd + idx] =
        hs[(size_t)(Lseq - 1) * (Hd * Bsz) + (size_t)h * Bsz + b];
}

// ---------------- launcher ----------------
extern "C" void kernel_launch(void* const* d_in, const int* in_sizes, int n_in,
                              void* d_out, int out_size)
{
    const float* x     = (const float*)d_in[0];
    const float* h0    = (const float*)d_in[1];
    const float* w_ih0 = (const float*)d_in[2];
    const float* w_hh0 = (const float*)d_in[3];
    const float* b_ih0 = (const float*)d_in[4];
    const float* b_hh0 = (const float*)d_in[5];
    const float* w_ih1 = (const float*)d_in[6];
    const float* w_hh1 = (const float*)d_in[7];
    const float* b_ih1 = (const float*)d_in[8];
    const float* b_hh1 = (const float*)d_in[9];
    float* out = (float*)d_out;

    const size_t smem = (6192 + 3072) * sizeof(u64) + (8192 + 768 + 32) * sizeof(float);
    cudaFuncSetAttribute(gru_recur_kernel,
                         cudaFuncAttributeMaxDynamicSharedMemorySize, (int)smem);

    gi_gemm_kernel<<<dim3(6, Lseq), 256>>>(x, w_ih0, b_ih0, 0);
    gru_recur_kernel<<<RBLK, 512, smem>>>(w_hh0, b_hh0, h0, 0);
    gi_gemm_kernel<<<dim3(6, Lseq), 256>>>(x, w_ih1, b_ih1, 1);
    gru_recur_kernel<<<RBLK, 512, smem>>>(w_hh1, b_hh1, h0, 1);
    transpose_out_kernel<<<dim3(8, Lseq), 256>>>(out);
    if (out_size >= (int)((size_t)Bsz * Lseq * Hd + 2 * Bsz * Hd))
        hn_kernel<<<256, 256>>>(out);
}